// round 13
// baseline (speedup 1.0000x reference)
#include <cuda_runtime.h>

// SSIM, fused single-pass box filters, 4 cols/lane, float4 loads, prefetched
// vertical updates, f32x2 packed math (Blackwell dual-fp32 pipe).
//
// img (16,3,512,512) f32; channel 0, crop 4 -> 504x504.
// 5 groups x 16 images x 36 strips(14 rows) = 2880 warps -> 720 blocks x 128.

#define IMG_STRIDE (3 * 512 * 512)
#define W4 128            // float4 per image row (512 floats)
#define OUTW 504
#define NGROUPS 5
#define STRIPS 36
#define STRIP_H 14        // 36*14 = 504
#define NWARPS (NGROUPS * 16 * STRIPS)      // 2880
#define WPB 4
#define NBLOCKS (NWARPS / WPB)              // 720

typedef unsigned long long u64;

__device__ float g_partials[NBLOCKS];
__device__ int   g_count = 0;

// ---- f32x2 packed helpers (sm_100+ PTX) ----
__device__ __forceinline__ u64 pk2(float lo, float hi) {
    u64 r; asm("mov.b64 %0, {%1, %2};" : "=l"(r) : "f"(lo), "f"(hi)); return r;
}
__device__ __forceinline__ void upk2(u64 v, float& lo, float& hi) {
    asm("mov.b64 {%0, %1}, %2;" : "=f"(lo), "=f"(hi) : "l"(v));
}
__device__ __forceinline__ u64 add2(u64 a, u64 b) {
    u64 r; asm("add.rn.f32x2 %0, %1, %2;" : "=l"(r) : "l"(a), "l"(b)); return r;
}
__device__ __forceinline__ u64 mul2(u64 a, u64 b) {
    u64 r; asm("mul.rn.f32x2 %0, %1, %2;" : "=l"(r) : "l"(a), "l"(b)); return r;
}
__device__ __forceinline__ u64 fma2(u64 a, u64 b, u64 c) {
    u64 r; asm("fma.rn.f32x2 %0, %1, %2, %3;" : "=l"(r) : "l"(a), "l"(b), "l"(c)); return r;
}

// Horizontal 11-window: lane L holds ext elems m=4L..4L+3 (v0..v3).
// W[k] = sum over ext m'=4L+k .. m'+10.
__device__ __forceinline__ void win4(float v0, float v1, float v2, float v3,
                                     float& W0, float& W1, float& W2, float& W3)
{
    const unsigned m = 0xffffffffu;
    const float p2 = v0 + v1;
    const float p3 = p2 + v2;
    const float T  = p3 + v3;
    const float suf1 = T - v0;
    const float suf2 = v2 + v3;
    const float Tn1  = __shfl_down_sync(m, T,  1);
    const float Tn2  = __shfl_down_sync(m, T,  2);
    const float p3n2 = __shfl_down_sync(m, p3, 2);
    const float p1n3 = __shfl_down_sync(m, v0, 3);
    const float p2n3 = __shfl_down_sync(m, p2, 3);
    const float TT = Tn1 + Tn2;
    W0 = T + Tn1 + p3n2;
    W1 = suf1 + TT;
    W2 = (suf2 + p1n3) + TT;
    W3 = (v3 + p2n3) + TT;
}

__global__ __launch_bounds__(128) void ssim_main(
    const float* __restrict__ img1, const float* __restrict__ img2,
    float* __restrict__ out)
{
    const int wib  = threadIdx.x >> 5;
    const int w    = blockIdx.x * WPB + wib;
    const int lane = threadIdx.x & 31;
    const int tid  = threadIdx.x;

    const int g     = w % NGROUPS;
    const int t     = w / NGROUPS;
    const int img   = t & 15;
    const int strip = t >> 4;

    // Aligned ext base; output range partition over groups.
    const int e0 = 116 * g - 8;
    const int lo = (g == 0) ? 0    : (116 * g - 3);
    const int hi = (g == 4) ? OUTW : (116 * g + 113);

    const int ec = e0 + 4 * lane;                  // lane's quad ext start
    const bool loadok = (ec >= 0) && (ec <= 500);  // whole quad in [0,504)

    float mk[4];
    #pragma unroll
    for (int k = 0; k < 4; ++k) {
        const int c = ec + 5 + k;                  // output col of W[k]
        mk[k] = ((c >= lo) && (c < hi)) ? 1.0f : 0.0f;
    }
    const u64 mk0 = pk2(mk[0], mk[1]);
    const u64 mk1 = pk2(mk[2], mk[3]);

    // Quad pointers: global col = ec + 4 (aligned); row r at +(r+4)*W4.
    const float4* q1 = reinterpret_cast<const float4*>(
        img1 + (size_t)img * IMG_STRIDE) + ((ec >> 2) + 1);
    const float4* q2 = reinterpret_cast<const float4*>(
        img2 + (size_t)img * IMG_STRIDE) + ((ec >> 2) + 1);

    const int r0 = strip * STRIP_H;

    // Packed vertical state: pairs (k0,k1) and (k2,k3).
    u64 V1p[2]  = {0ull, 0ull};
    u64 V2p[2]  = {0ull, 0ull};
    u64 Vssp[2] = {0ull, 0ull};
    u64 V12p[2] = {0ull, 0ull};

    // Prologue: V = rows r0-5 .. r0+5 (zero-padded below 0).
    {
        const float4* pP1 = q1 + (ptrdiff_t)(r0 - 1) * W4;   // row r0-5
        const float4* pP2 = q2 + (ptrdiff_t)(r0 - 1) * W4;
        #pragma unroll
        for (int j = 0; j < 11; ++j) {
            const int r = r0 - 5 + j;
            float4 a = {0.f,0.f,0.f,0.f}, b = {0.f,0.f,0.f,0.f};
            if (loadok && r >= 0) { a = __ldg(pP1); b = __ldg(pP2); }
            pP1 += W4; pP2 += W4;
            const u64 a01 = pk2(a.x, a.y), a23 = pk2(a.z, a.w);
            const u64 b01 = pk2(b.x, b.y), b23 = pk2(b.z, b.w);
            V1p[0]  = add2(V1p[0], a01);  V1p[1]  = add2(V1p[1], a23);
            V2p[0]  = add2(V2p[0], b01);  V2p[1]  = add2(V2p[1], b23);
            Vssp[0] = fma2(a01, a01, Vssp[0]); Vssp[0] = fma2(b01, b01, Vssp[0]);
            Vssp[1] = fma2(a23, a23, Vssp[1]); Vssp[1] = fma2(b23, b23, Vssp[1]);
            V12p[0] = fma2(a01, b01, V12p[0]); V12p[1] = fma2(a23, b23, V12p[1]);
        }
    }

    // Packed constants (121-scaled SSIM domain; num/den both scaled 121^4).
    const float C1K = 6.5025f  * 14641.f;
    const float C2K = 58.5225f * 14641.f;
    const u64 C1Kp  = pk2(C1K, C1K);
    const u64 C2Kp  = pk2(C2K, C2K);
    const u64 K121p = pk2(121.f, 121.f);
    const u64 K242p = pk2(242.f, 242.f);
    const u64 TWOp  = pk2(2.f, 2.f);
    const u64 NEG1p = pk2(-1.f, -1.f);
    const u64 NEG2p = pk2(-2.f, -2.f);

    u64 acc0 = 0ull, acc1 = 0ull;

    const float4* pA1 = q1 + (ptrdiff_t)(r0 + 10) * W4;  // admit row r0+6
    const float4* pA2 = q2 + (ptrdiff_t)(r0 + 10) * W4;
    const float4* pR1 = q1 + (ptrdiff_t)(r0 - 1)  * W4;  // retire row r0-5
    const float4* pR2 = q2 + (ptrdiff_t)(r0 - 1)  * W4;

    #pragma unroll 2
    for (int i = 0; i < STRIP_H; ++i) {
        const int y = r0 + i;

        // Issue next-state loads FIRST (consumed much later).
        float4 na = {0.f,0.f,0.f,0.f}, nb = {0.f,0.f,0.f,0.f};
        float4 oa = {0.f,0.f,0.f,0.f}, ob = {0.f,0.f,0.f,0.f};
        if (loadok && y <= OUTW - 7) { na = __ldg(pA1); nb = __ldg(pA2); }
        if (loadok && y >= 5)        { oa = __ldg(pR1); ob = __ldg(pR2); }
        pA1 += W4; pA2 += W4; pR1 += W4; pR2 += W4;

        // Horizontal windows on CURRENT vertical state (scalar views are
        // register-pair aliases; no dependence on the loads above).
        float B1[4], B2[4], Bss[4], B12[4];
        {
            float x0,x1,x2,x3;
            upk2(V1p[0], x0,x1); upk2(V1p[1], x2,x3);
            win4(x0,x1,x2,x3, B1[0],B1[1],B1[2],B1[3]);
            upk2(V2p[0], x0,x1); upk2(V2p[1], x2,x3);
            win4(x0,x1,x2,x3, B2[0],B2[1],B2[2],B2[3]);
            upk2(Vssp[0], x0,x1); upk2(Vssp[1], x2,x3);
            win4(x0,x1,x2,x3, Bss[0],Bss[1],Bss[2],Bss[3]);
            upk2(V12p[0], x0,x1); upk2(V12p[1], x2,x3);
            win4(x0,x1,x2,x3, B12[0],B12[1],B12[2],B12[3]);
        }

        // SSIM, packed over pixel pairs.
        #pragma unroll
        for (int p = 0; p < 2; ++p) {
            const u64 B1p  = pk2(B1[2*p],  B1[2*p+1]);
            const u64 B2p  = pk2(B2[2*p],  B2[2*p+1]);
            const u64 Bssp2= pk2(Bss[2*p], Bss[2*p+1]);
            const u64 B12p = pk2(B12[2*p], B12[2*p+1]);

            const u64 P    = mul2(B1p, B2p);
            const u64 Q    = fma2(B1p, B1p, mul2(B2p, B2p));
            const u64 m2   = fma2(P, NEG2p, C2Kp);       // C2K - 2P
            const u64 num2 = fma2(K242p, B12p, m2);      // 2*t12 + C2K
            const u64 num1 = fma2(TWOp, P, C1Kp);        // 2P + C1K
            const u64 num  = mul2(num1, num2);
            const u64 qd   = add2(Q, C1Kp);              // Q + C1K
            const u64 tdn  = fma2(Q, NEG1p, C2Kp);       // C2K - Q
            const u64 td   = fma2(K121p, Bssp2, tdn);    // tss + C2K
            const u64 den  = mul2(qd, td);
            float dlo, dhi, rlo, rhi;
            upk2(den, dlo, dhi);
            asm("rcp.approx.f32 %0, %1;" : "=f"(rlo) : "f"(dlo));
            asm("rcp.approx.f32 %0, %1;" : "=f"(rhi) : "f"(dhi));
            const u64 r = mul2(num, pk2(rlo, rhi));
            if (p == 0) acc0 = fma2(r, mk0, acc0);
            else        acc1 = fma2(r, mk1, acc1);
        }

        // Vertical update V(y) -> V(y+1), packed.
        // a^2 - o^2 = (a-o)(a+o); d = a-o also drives the V1/V2 update.
        {
            const u64 na01 = pk2(na.x, na.y), na23 = pk2(na.z, na.w);
            const u64 nb01 = pk2(nb.x, nb.y), nb23 = pk2(nb.z, nb.w);
            const u64 oa01 = pk2(oa.x, oa.y), oa23 = pk2(oa.z, oa.w);
            const u64 ob01 = pk2(ob.x, ob.y), ob23 = pk2(ob.z, ob.w);

            const u64 da0 = fma2(oa01, NEG1p, na01);  // na - oa
            const u64 sa0 = add2(na01, oa01);
            const u64 db0 = fma2(ob01, NEG1p, nb01);
            const u64 sb0 = add2(nb01, ob01);
            V1p[0]  = add2(V1p[0], da0);
            V2p[0]  = add2(V2p[0], db0);
            Vssp[0] = fma2(da0, sa0, Vssp[0]);
            Vssp[0] = fma2(db0, sb0, Vssp[0]);
            V12p[0] = fma2(na01, nb01, V12p[0]);
            const u64 t0 = mul2(oa01, ob01);
            V12p[0] = fma2(t0, NEG1p, V12p[0]);

            const u64 da1 = fma2(oa23, NEG1p, na23);
            const u64 sa1 = add2(na23, oa23);
            const u64 db1 = fma2(ob23, NEG1p, nb23);
            const u64 sb1 = add2(nb23, ob23);
            V1p[1]  = add2(V1p[1], da1);
            V2p[1]  = add2(V2p[1], db1);
            Vssp[1] = fma2(da1, sa1, Vssp[1]);
            Vssp[1] = fma2(db1, sb1, Vssp[1]);
            V12p[1] = fma2(na23, nb23, V12p[1]);
            const u64 t1 = mul2(oa23, ob23);
            V12p[1] = fma2(t1, NEG1p, V12p[1]);
        }
    }

    // ---- block partial + fused final reduction ----
    float a0, a1, a2, a3;
    upk2(acc0, a0, a1); upk2(acc1, a2, a3);
    float acc = (a0 + a1) + (a2 + a3);
    #pragma unroll
    for (int d = 16; d; d >>= 1)
        acc += __shfl_xor_sync(0xffffffffu, acc, d);

    __shared__ float sp[WPB];
    __shared__ int   isLast;
    if (lane == 0) sp[wib] = acc;
    __syncthreads();
    if (tid == 0) {
        g_partials[blockIdx.x] = sp[0] + sp[1] + sp[2] + sp[3];
        __threadfence();
        isLast = (atomicAdd(&g_count, 1) == NBLOCKS - 1);
    }
    __syncthreads();

    if (isLast) {
        float v = 0.f;
        for (int i = tid; i < NBLOCKS; i += 128)
            v += __ldcg(&g_partials[i]);
        #pragma unroll
        for (int d = 16; d; d >>= 1)
            v += __shfl_xor_sync(0xffffffffu, v, d);
        if (lane == 0) sp[wib] = v;
        __syncthreads();
        if (tid == 0) {
            out[0] = (sp[0] + sp[1] + sp[2] + sp[3]) * (1.0f / 4064256.0f);
            g_count = 0;   // reset for next graph replay
        }
    }
}

extern "C" void kernel_launch(void* const* d_in, const int* in_sizes, int n_in,
                              void* d_out, int out_size)
{
    const float* img1 = (const float*)d_in[0];
    const float* img2 = (const float*)d_in[1];
    float* out = (float*)d_out;
    ssim_main<<<NBLOCKS, 128>>>(img1, img2, out);
}

// round 14
// speedup vs baseline: 1.1216x; 1.1216x over previous
#include <cuda_runtime.h>

// SSIM, fused single-pass box filters, 4 cols/lane, aligned float4 loads,
// software-prefetched vertical updates, paired reciprocals.
//
// img (16,3,512,512) f32; channel 0, crop 4 -> 504x504.
// Groups: ext base e0 = 116g-8 (16B-aligned quads per lane); each warp holds
// 128 ext cols, computes 118 windows; per-element ov ranges partition [0,504).
// Vertical 11-row running sums; per iteration: issue admit/retire loads FIRST
// (retire = admit pointer - 11 rows, immediate offset), then win4 + SSIM on
// current state, then apply updates. One MUFU.RCP per 2 pixels.
// 5 groups x 16 images x 36 strips(14 rows) = 2880 warps -> 720 blocks x 128.

#define IMG_STRIDE (3 * 512 * 512)
#define W4 128            // float4 per image row (512 floats)
#define OUTW 504
#define NGROUPS 5
#define STRIPS 36
#define STRIP_H 14        // 36*14 = 504
#define NWARPS (NGROUPS * 16 * STRIPS)      // 2880
#define WPB 4
#define NBLOCKS (NWARPS / WPB)              // 720
#define RETIRE_OFF (11 * W4)                // retire row = admit row - 11

__device__ float g_partials[NBLOCKS];
__device__ int   g_count = 0;

__device__ __forceinline__ float rcp_approx(float x) {
    float r; asm("rcp.approx.f32 %0, %1;" : "=f"(r) : "f"(x)); return r;
}

// Horizontal 11-window: lane L holds ext elems m=4L..4L+3 (v0..v3).
// W[k] = sum over ext m'=4L+k .. m'+10.
__device__ __forceinline__ void win4(float v0, float v1, float v2, float v3,
                                     float& W0, float& W1, float& W2, float& W3)
{
    const unsigned m = 0xffffffffu;
    const float p2 = v0 + v1;
    const float p3 = p2 + v2;
    const float T  = p3 + v3;
    const float suf1 = T - v0;
    const float suf2 = v2 + v3;
    const float Tn1  = __shfl_down_sync(m, T,  1);
    const float Tn2  = __shfl_down_sync(m, T,  2);
    const float p3n2 = __shfl_down_sync(m, p3, 2);
    const float p1n3 = __shfl_down_sync(m, v0, 3);
    const float p2n3 = __shfl_down_sync(m, p2, 3);
    const float TT = Tn1 + Tn2;
    W0 = T + Tn1 + p3n2;
    W1 = suf1 + TT;
    W2 = (suf2 + p1n3) + TT;
    W3 = (v3 + p2n3) + TT;
}

#define ADMIT(k, av, bv)                                     \
    V1[k] += (av); V2[k] += (bv);                            \
    Vss[k] = fmaf((av), (av), Vss[k]);                       \
    Vss[k] = fmaf((bv), (bv), Vss[k]);                       \
    V12[k] = fmaf((av), (bv), V12[k]);

#define UPDATE(k, an, bn, ao, bo)                            \
    V1[k] += (an) - (ao); V2[k] += (bn) - (bo);              \
    Vss[k] = fmaf((an), (an), Vss[k]);                       \
    Vss[k] = fmaf((bn), (bn), Vss[k]);                       \
    Vss[k] = fmaf(-(ao), (ao), Vss[k]);                      \
    Vss[k] = fmaf(-(bo), (bo), Vss[k]);                      \
    V12[k] = fmaf((an), (bn), V12[k]);                       \
    V12[k] = fmaf(-(ao), (bo), V12[k]);

__global__ __launch_bounds__(128) void ssim_main(
    const float* __restrict__ img1, const float* __restrict__ img2,
    float* __restrict__ out)
{
    const int wib  = threadIdx.x >> 5;
    const int w    = blockIdx.x * WPB + wib;
    const int lane = threadIdx.x & 31;
    const int tid  = threadIdx.x;

    const int g     = w % NGROUPS;
    const int t     = w / NGROUPS;
    const int img   = t & 15;
    const int strip = t >> 4;

    // Aligned ext base; output range partition over groups.
    const int e0 = 116 * g - 8;
    const int lo = (g == 0) ? 0    : (116 * g - 3);
    const int hi = (g == 4) ? OUTW : (116 * g + 113);

    const int ec = e0 + 4 * lane;                  // lane's quad ext start
    const bool loadok = (ec >= 0) && (ec <= 500);  // whole quad in [0,504)

    bool ov[4];
    #pragma unroll
    for (int k = 0; k < 4; ++k) {
        const int c = ec + 5 + k;                  // output col of W[k]
        ov[k] = (c >= lo) && (c < hi);
    }

    // Quad pointers: global col = ec + 4 (aligned); row r at +(r+4)*W4.
    const float4* q1 = reinterpret_cast<const float4*>(
        img1 + (size_t)img * IMG_STRIDE) + ((ec >> 2) + 1);
    const float4* q2 = reinterpret_cast<const float4*>(
        img2 + (size_t)img * IMG_STRIDE) + ((ec >> 2) + 1);

    const int r0 = strip * STRIP_H;

    float V1[4]  = {0.f, 0.f, 0.f, 0.f};
    float V2[4]  = {0.f, 0.f, 0.f, 0.f};
    float Vss[4] = {0.f, 0.f, 0.f, 0.f};
    float V12[4] = {0.f, 0.f, 0.f, 0.f};

    // Prologue: V = rows r0-5 .. r0+5 (zero-padded below 0).
    {
        const float4* pP1 = q1 + (ptrdiff_t)(r0 - 1) * W4;   // row r0-5
        const float4* pP2 = q2 + (ptrdiff_t)(r0 - 1) * W4;
        #pragma unroll
        for (int j = 0; j < 11; ++j) {
            const int r = r0 - 5 + j;
            float4 a = {0.f,0.f,0.f,0.f}, b = {0.f,0.f,0.f,0.f};
            if (loadok && r >= 0) { a = __ldg(pP1); b = __ldg(pP2); }
            pP1 += W4; pP2 += W4;
            ADMIT(0, a.x, b.x) ADMIT(1, a.y, b.y)
            ADMIT(2, a.z, b.z) ADMIT(3, a.w, b.w)
        }
    }

    const float C1K = 6.5025f  * 14641.f;   // C1 * 121^2
    const float C2K = 58.5225f * 14641.f;   // C2 * 121^2
    float acc = 0.f;

    const float4* pA1 = q1 + (ptrdiff_t)(r0 + 10) * W4;  // admit row r0+6
    const float4* pA2 = q2 + (ptrdiff_t)(r0 + 10) * W4;  // (retire = -11 rows)

    #pragma unroll 2
    for (int i = 0; i < STRIP_H; ++i) {
        const int y = r0 + i;

        // Issue next-state loads FIRST (consumed ~150 instrs later).
        // Retire loads use an immediate offset from the admit pointers.
        float4 na = {0.f,0.f,0.f,0.f}, nb = {0.f,0.f,0.f,0.f};
        float4 oa = {0.f,0.f,0.f,0.f}, ob = {0.f,0.f,0.f,0.f};
        if (loadok && y <= OUTW - 7) { na = __ldg(pA1); nb = __ldg(pA2); }
        if (loadok && y >= 5) {
            oa = __ldg(pA1 - RETIRE_OFF);   // row y-5 (L1 hit, 11-row reuse)
            ob = __ldg(pA2 - RETIRE_OFF);
        }
        pA1 += W4; pA2 += W4;

        // Horizontal windows on CURRENT vertical state (no dep on loads).
        float B1[4], B2[4], Bss[4], B12[4];
        win4(V1[0],  V1[1],  V1[2],  V1[3],  B1[0],  B1[1],  B1[2],  B1[3]);
        win4(V2[0],  V2[1],  V2[2],  V2[3],  B2[0],  B2[1],  B2[2],  B2[3]);
        win4(Vss[0], Vss[1], Vss[2], Vss[3], Bss[0], Bss[1], Bss[2], Bss[3]);
        win4(V12[0], V12[1], V12[2], V12[3], B12[0], B12[1], B12[2], B12[3]);

        // SSIM in 121-scaled domain; one reciprocal per 2 pixels:
        // acc += n0/d0 + n1/d1 = (n0*d1 + n1*d0) * rcp(d0*d1)
        float nm[4], dn[4];
        #pragma unroll
        for (int k = 0; k < 4; ++k) {
            const float P   = B1[k] * B2[k];
            const float Q   = fmaf(B1[k], B1[k], B2[k] * B2[k]);
            const float t12 = fmaf(121.f, B12[k], -P);
            const float tss = fmaf(121.f, Bss[k], -Q);
            nm[k] = fmaf(2.f, P, C1K) * fmaf(2.f, t12, C2K);
            dn[k] = (Q + C1K) * (tss + C2K);
        }
        #pragma unroll
        for (int p = 0; p < 2; ++p) {
            const int k0 = 2 * p, k1 = 2 * p + 1;
            const float rr = rcp_approx(dn[k0] * dn[k1]);
            const float t0 = nm[k0] * dn[k1];
            const float t1 = nm[k1] * dn[k0];
            if (ov[k0]) acc = fmaf(t0, rr, acc);
            if (ov[k1]) acc = fmaf(t1, rr, acc);
        }

        // Apply vertical update: V(y) -> V(y+1).
        UPDATE(0, na.x, nb.x, oa.x, ob.x)
        UPDATE(1, na.y, nb.y, oa.y, ob.y)
        UPDATE(2, na.z, nb.z, oa.z, ob.z)
        UPDATE(3, na.w, nb.w, oa.w, ob.w)
    }

    // ---- block partial + fused final reduction ----
    #pragma unroll
    for (int d = 16; d; d >>= 1)
        acc += __shfl_xor_sync(0xffffffffu, acc, d);

    __shared__ float sp[WPB];
    __shared__ int   isLast;
    if (lane == 0) sp[wib] = acc;
    __syncthreads();
    if (tid == 0) {
        g_partials[blockIdx.x] = sp[0] + sp[1] + sp[2] + sp[3];
        __threadfence();
        isLast = (atomicAdd(&g_count, 1) == NBLOCKS - 1);
    }
    __syncthreads();

    if (isLast) {
        float v = 0.f;
        for (int i = tid; i < NBLOCKS; i += 128)
            v += __ldcg(&g_partials[i]);
        #pragma unroll
        for (int d = 16; d; d >>= 1)
            v += __shfl_xor_sync(0xffffffffu, v, d);
        if (lane == 0) sp[wib] = v;
        __syncthreads();
        if (tid == 0) {
            out[0] = (sp[0] + sp[1] + sp[2] + sp[3]) * (1.0f / 4064256.0f);
            g_count = 0;   // reset for next graph replay
        }
    }
}

extern "C" void kernel_launch(void* const* d_in, const int* in_sizes, int n_in,
                              void* d_out, int out_size)
{
    const float* img1 = (const float*)d_in[0];
    const float* img2 = (const float*)d_in[1];
    float* out = (float*)d_out;
    ssim_main<<<NBLOCKS, 128>>>(img1, img2, out);
}